// round 1
// baseline (speedup 1.0000x reference)
#include <cuda_runtime.h>
#include <math.h>

#define NN 50000
#define EE 800000
#define FIN 10
#define HH 64
#define LL 3

__device__ float d_h[NN * HH];
__device__ float d_agg[NN * HH];
__device__ float d_cnt[NN];

// ---------------------------------------------------------------------------
// Kernel 1: h = relu(x @ Wp + bp)   (N,10)@(10,64)
// ---------------------------------------------------------------------------
__global__ void proj_kernel(const float* __restrict__ x,
                            const float* __restrict__ Wp,
                            const float* __restrict__ bp) {
    __shared__ float Ws[FIN * HH];
    __shared__ float bs[HH];
    for (int i = threadIdx.x; i < FIN * HH; i += blockDim.x) Ws[i] = Wp[i];
    if (threadIdx.x < HH) bs[threadIdx.x] = bp[threadIdx.x];
    __syncthreads();

    int idx = blockIdx.x * blockDim.x + threadIdx.x;
    if (idx >= NN * HH) return;
    int i = idx >> 6;
    int j = idx & 63;
    float acc = bs[j];
#pragma unroll
    for (int k = 0; k < FIN; k++) acc = fmaf(x[i * FIN + k], Ws[k * HH + j], acc);
    d_h[idx] = fmaxf(acc, 0.f);
}

// ---------------------------------------------------------------------------
// Kernel 2 (per layer): fused edge-gate MLP + gather/scale/scatter.
// One warp per edge. Lanes 0..15 each compute one hidden unit of the
// 3->16->1 MLP, warp-reduce, sigmoid -> ew. Then lanes gather h[src]
// (2 floats/lane), scale by ew, atomicAdd into agg[dst]; lane 0 adds cnt.
// ---------------------------------------------------------------------------
__global__ void scatter_kernel(const int* __restrict__ ei,
                               const float* __restrict__ ea,
                               const float* __restrict__ w1,
                               const float* __restrict__ b1,
                               const float* __restrict__ w2,
                               const float* __restrict__ b2) {
    int e = (blockIdx.x * blockDim.x + threadIdx.x) >> 5;
    int lane = threadIdx.x & 31;
    if (e >= EE) return;

    float a0 = ea[e * 3 + 0];
    float a1 = ea[e * 3 + 1];
    float a2 = ea[e * 3 + 2];

    float partial = 0.f;
    if (lane < 16) {
        float hk = b1[lane];
        hk = fmaf(a0, w1[0 * 16 + lane], hk);
        hk = fmaf(a1, w1[1 * 16 + lane], hk);
        hk = fmaf(a2, w1[2 * 16 + lane], hk);
        hk = fmaxf(hk, 0.f);
        partial = hk * w2[lane];
    }
#pragma unroll
    for (int o = 16; o > 0; o >>= 1)
        partial += __shfl_xor_sync(0xffffffffu, partial, o);
    float z = partial + b2[0];
    float ew = 1.f / (1.f + __expf(-z));

    int s = ei[e];        // row 0 of (2,E)
    int d = ei[EE + e];   // row 1

    float v0 = d_h[s * HH + lane] * ew;
    float v1 = d_h[s * HH + 32 + lane] * ew;
    atomicAdd(&d_agg[d * HH + lane], v0);
    atomicAdd(&d_agg[d * HH + 32 + lane], v1);
    if (lane == 0) atomicAdd(&d_cnt[d], ew);
}

// ---------------------------------------------------------------------------
// Kernel 3 (per layer): node update.
// agg /= max(cnt,eps); upd = relu([h,agg] @ nw + nb); h = LN(h+upd)*g+b.
// 4 nodes per 256-thread block iteration, weights (128x64=32KB) in smem.
// ---------------------------------------------------------------------------
__global__ void update_kernel(const float* __restrict__ nw,
                              const float* __restrict__ nb,
                              const float* __restrict__ g,
                              const float* __restrict__ b) {
    __shared__ float Ws[2 * HH * HH];          // 32 KB
    __shared__ float nbs[HH], gs[HH], bs[HH];
    __shared__ float ins[4][2 * HH];
    __shared__ float red1[8], red2[8];

    for (int i = threadIdx.x; i < 2 * HH * HH; i += blockDim.x) Ws[i] = nw[i];
    if (threadIdx.x < HH) {
        nbs[threadIdx.x] = nb[threadIdx.x];
        gs[threadIdx.x] = g[threadIdx.x];
        bs[threadIdx.x] = b[threadIdx.x];
    }
    __syncthreads();

    int sub  = threadIdx.x >> 6;   // 0..3 : node within group
    int j    = threadIdx.x & 63;   // output feature
    int warp = threadIdx.x >> 5;   // 0..7
    int lane = threadIdx.x & 31;

    for (int base = blockIdx.x * 4; base < NN; base += gridDim.x * 4) {
        int node = base + sub;     // NN % 4 == 0, always valid

        float hv = d_h[node * HH + j];
        float c = d_cnt[node];
        float av = d_agg[node * HH + j] / fmaxf(c, 1e-12f);
        ins[sub][j]      = hv;
        ins[sub][HH + j] = av;
        __syncthreads();

        float acc = nbs[j];
#pragma unroll 8
        for (int k = 0; k < 2 * HH; k++)
            acc = fmaf(ins[sub][k], Ws[k * HH + j], acc);
        float v = hv + fmaxf(acc, 0.f);

        // --- LayerNorm over 64 features (2 warps per node) ---
        float s1 = v;
#pragma unroll
        for (int o = 16; o > 0; o >>= 1)
            s1 += __shfl_xor_sync(0xffffffffu, s1, o);
        if (lane == 0) red1[warp] = s1;
        __syncthreads();
        float mu = (red1[2 * sub] + red1[2 * sub + 1]) * (1.f / HH);

        float t = v - mu;
        float s2 = t * t;
#pragma unroll
        for (int o = 16; o > 0; o >>= 1)
            s2 += __shfl_xor_sync(0xffffffffu, s2, o);
        if (lane == 0) red2[warp] = s2;
        __syncthreads();
        float var = (red2[2 * sub] + red2[2 * sub + 1]) * (1.f / HH);

        d_h[node * HH + j] = t * rsqrtf(var + 1e-5f) * gs[j] + bs[j];
        __syncthreads();
    }
}

// ---------------------------------------------------------------------------
// Kernel 4: head.  out = relu(h @ hw1 + hb1) @ hw2 + hb2
// One warp per node: lane t computes hidden unit t (t<32), then warp-reduce.
// ---------------------------------------------------------------------------
__global__ void head_kernel(const float* __restrict__ hw1,
                            const float* __restrict__ hb1,
                            const float* __restrict__ hw2,
                            const float* __restrict__ hb2,
                            float* __restrict__ out) {
    __shared__ float W1[HH * 32];   // 8 KB
    __shared__ float b1s[32], w2s[32];
    for (int i = threadIdx.x; i < HH * 32; i += blockDim.x) W1[i] = hw1[i];
    if (threadIdx.x < 32) {
        b1s[threadIdx.x] = hb1[threadIdx.x];
        w2s[threadIdx.x] = hw2[threadIdx.x];
    }
    __syncthreads();

    int lane = threadIdx.x & 31;
    int warp = threadIdx.x >> 5;
    float bb2 = hb2[0];

    for (int node = blockIdx.x * 8 + warp; node < NN; node += gridDim.x * 8) {
        // stage h row into registers coalesced, distribute via shuffle
        float hlo = d_h[node * HH + lane];
        float hhi = d_h[node * HH + 32 + lane];
        float acc = b1s[lane];
#pragma unroll
        for (int k = 0; k < 32; k++) {
            float hk = __shfl_sync(0xffffffffu, hlo, k);
            acc = fmaf(hk, W1[k * 32 + lane], acc);
        }
#pragma unroll
        for (int k = 0; k < 32; k++) {
            float hk = __shfl_sync(0xffffffffu, hhi, k);
            acc = fmaf(hk, W1[(32 + k) * 32 + lane], acc);
        }
        float p = fmaxf(acc, 0.f) * w2s[lane];
#pragma unroll
        for (int o = 16; o > 0; o >>= 1)
            p += __shfl_xor_sync(0xffffffffu, p, o);
        if (lane == 0) out[node] = p + bb2;
    }
}

// ---------------------------------------------------------------------------
extern "C" void kernel_launch(void* const* d_in, const int* in_sizes, int n_in,
                              void* d_out, int out_size) {
    const float* x   = (const float*)d_in[0];
    const int*   ei  = (const int*)  d_in[1];
    const float* ea  = (const float*)d_in[2];
    const float* Wp  = (const float*)d_in[3];
    const float* bp  = (const float*)d_in[4];
    const float* ew1 = (const float*)d_in[5];
    const float* eb1 = (const float*)d_in[6];
    const float* ew2 = (const float*)d_in[7];
    const float* eb2 = (const float*)d_in[8];
    const float* nw  = (const float*)d_in[9];
    const float* nb  = (const float*)d_in[10];
    const float* lng = (const float*)d_in[11];
    const float* lnb = (const float*)d_in[12];
    const float* hw1 = (const float*)d_in[13];
    const float* hb1 = (const float*)d_in[14];
    const float* hw2 = (const float*)d_in[15];
    const float* hb2 = (const float*)d_in[16];
    float* out = (float*)d_out;

    void* aggPtr = nullptr;
    void* cntPtr = nullptr;
    cudaGetSymbolAddress(&aggPtr, d_agg);
    cudaGetSymbolAddress(&cntPtr, d_cnt);

    proj_kernel<<<(NN * HH + 255) / 256, 256>>>(x, Wp, bp);

    for (int l = 0; l < LL; l++) {
        cudaMemsetAsync(aggPtr, 0, (size_t)NN * HH * sizeof(float));
        cudaMemsetAsync(cntPtr, 0, (size_t)NN * sizeof(float));
        scatter_kernel<<<(EE * 32 + 255) / 256, 256>>>(
            ei, ea, ew1 + l * 3 * 16, eb1 + l * 16, ew2 + l * 16, eb2 + l);
        update_kernel<<<592, 256>>>(
            nw + l * 2 * HH * HH, nb + l * HH, lng + l * HH, lnb + l * HH);
    }

    head_kernel<<<592, 256>>>(hw1, hb1, hw2, hb2, out);
}

// round 3
// speedup vs baseline: 1.3015x; 1.3015x over previous
#include <cuda_runtime.h>
#include <math.h>

#define NN 50000
#define EE 800000
#define FIN 10
#define HH 64
#define LL 3

__device__ float d_hA[NN * HH];
__device__ float d_hB[NN * HH];
__device__ float d_ew[LL * EE];        // per-layer edge gates
__device__ int   d_deg[NN];
__device__ int   d_off[NN + 1];
__device__ int   d_cur[NN];
__device__ int2  d_list[EE];           // {src, edge_id} bucketed by dst

// ---------------------------------------------------------------------------
// Kernel: h = relu(x @ Wp + bp)
// ---------------------------------------------------------------------------
__global__ void proj_kernel(const float* __restrict__ x,
                            const float* __restrict__ Wp,
                            const float* __restrict__ bp) {
    __shared__ float Ws[FIN * HH];
    __shared__ float bs[HH];
    for (int i = threadIdx.x; i < FIN * HH; i += blockDim.x) Ws[i] = Wp[i];
    if (threadIdx.x < HH) bs[threadIdx.x] = bp[threadIdx.x];
    __syncthreads();

    int idx = blockIdx.x * blockDim.x + threadIdx.x;
    if (idx >= NN * HH) return;
    int i = idx >> 6;
    int j = idx & 63;
    float acc = bs[j];
#pragma unroll
    for (int k = 0; k < FIN; k++) acc = fmaf(x[i * FIN + k], Ws[k * HH + j], acc);
    d_hA[idx] = fmaxf(acc, 0.f);
}

// ---------------------------------------------------------------------------
// Kernel: all 3 layers' edge gates in one pass (independent of h).
// ---------------------------------------------------------------------------
__global__ void gate_kernel(const float* __restrict__ ea,
                            const float* __restrict__ ew1,
                            const float* __restrict__ eb1,
                            const float* __restrict__ ew2,
                            const float* __restrict__ eb2) {
    __shared__ float W1[LL * 3 * 16];
    __shared__ float B1[LL * 16];
    __shared__ float W2[LL * 16];
    __shared__ float B2[LL];
    for (int i = threadIdx.x; i < LL * 3 * 16; i += blockDim.x) W1[i] = ew1[i];
    if (threadIdx.x < LL * 16) {
        B1[threadIdx.x] = eb1[threadIdx.x];
        W2[threadIdx.x] = ew2[threadIdx.x];
    }
    if (threadIdx.x < LL) B2[threadIdx.x] = eb2[threadIdx.x];
    __syncthreads();

    int e = blockIdx.x * blockDim.x + threadIdx.x;   // EE % 256 == 0
    float a0 = ea[e * 3 + 0];
    float a1 = ea[e * 3 + 1];
    float a2 = ea[e * 3 + 2];
#pragma unroll
    for (int l = 0; l < LL; l++) {
        float z = B2[l];
#pragma unroll
        for (int k = 0; k < 16; k++) {
            float hk = B1[l * 16 + k];
            hk = fmaf(a0, W1[l * 48 + 0 * 16 + k], hk);
            hk = fmaf(a1, W1[l * 48 + 1 * 16 + k], hk);
            hk = fmaf(a2, W1[l * 48 + 2 * 16 + k], hk);
            z = fmaf(fmaxf(hk, 0.f), W2[l * 16 + k], z);
        }
        d_ew[l * EE + e] = 1.f / (1.f + __expf(-z));
    }
}

// ---------------------------------------------------------------------------
// CSR build
// ---------------------------------------------------------------------------
__global__ void count_kernel(const int* __restrict__ ei) {
    int e = blockIdx.x * blockDim.x + threadIdx.x;
    if (e >= EE) return;
    atomicAdd(&d_deg[ei[EE + e]], 1);
}

__global__ void scan_kernel() {   // 1 block, 1024 threads
    const int CH = (NN + 1023) / 1024;   // 49
    __shared__ int sm[1024];
    int t = threadIdx.x;
    int start = t * CH;
    int sum = 0;
    for (int i = 0; i < CH; i++) {
        int idx = start + i;
        if (idx < NN) sum += d_deg[idx];
    }
    sm[t] = sum;
    __syncthreads();
    for (int o = 1; o < 1024; o <<= 1) {
        int v = (t >= o) ? sm[t - o] : 0;
        __syncthreads();
        sm[t] += v;
        __syncthreads();
    }
    int run = sm[t] - sum;   // exclusive base
    for (int i = 0; i < CH; i++) {
        int idx = start + i;
        if (idx < NN) {
            d_off[idx] = run;
            d_cur[idx] = run;
            run += d_deg[idx];
        }
    }
    if (t == 1023) d_off[NN] = sm[1023];
}

__global__ void fill_kernel(const int* __restrict__ ei) {
    int e = blockIdx.x * blockDim.x + threadIdx.x;
    if (e >= EE) return;
    int s = ei[e];
    int d = ei[EE + e];
    int p = atomicAdd(&d_cur[d], 1);
    d_list[p] = make_int2(s, e);
}

// ---------------------------------------------------------------------------
// Fused per-layer kernel: warp per dst node.
//   agg/cnt accumulated in registers from CSR gather, then node MLP
//   (weights in smem), residual + LayerNorm, write to hout.
// ---------------------------------------------------------------------------
__global__ void __launch_bounds__(256)
layer_kernel(const float4* __restrict__ hin4,
             const float*  __restrict__ hin,
             float* __restrict__ hout,
             const float* __restrict__ ewl,
             const float* __restrict__ nw,
             const float* __restrict__ nb,
             const float* __restrict__ g,
             const float* __restrict__ b) {
    __shared__ float Ws[2 * HH * HH];      // 32 KB
    __shared__ float nbs[HH], gs[HH], bs[HH];
    for (int i = threadIdx.x; i < 2 * HH * HH; i += blockDim.x) Ws[i] = nw[i];
    if (threadIdx.x < HH) {
        nbs[threadIdx.x] = nb[threadIdx.x];
        gs[threadIdx.x]  = g[threadIdx.x];
        bs[threadIdx.x]  = b[threadIdx.x];
    }
    __syncthreads();

    int warp = threadIdx.x >> 5;
    int lane = threadIdx.x & 31;
    int q    = lane & 15;      // float4 slot within a 64-float row
    int half = lane >> 4;      // 0: even edges, 1: odd edges

    for (int nd = blockIdx.x * 8 + warp; nd < NN; nd += gridDim.x * 8) {
        int e0 = d_off[nd];
        int e1 = d_off[nd + 1];

        float acc0 = 0.f, acc1 = 0.f, acc2 = 0.f, acc3 = 0.f;
        float cw = 0.f;

        for (int base = e0; base < e1; base += 32) {
            int n = e1 - base;
            if (n > 32) n = 32;
            int2 le = make_int2(0, 0);
            float w = 0.f;
            if (lane < n) {
                le = d_list[base + lane];
                w = ewl[le.y];
            }
            cw += w;
            for (int i = 0; i < n; i += 2) {
                int idx = i + half;
                int   s  = __shfl_sync(0xffffffffu, le.x, idx);
                float wi = __shfl_sync(0xffffffffu, w, idx);
                if (idx < n) {
                    float4 v = hin4[s * 16 + q];
                    acc0 = fmaf(v.x, wi, acc0);
                    acc1 = fmaf(v.y, wi, acc1);
                    acc2 = fmaf(v.z, wi, acc2);
                    acc3 = fmaf(v.w, wi, acc3);
                }
            }
        }
        // combine the two half-warp partials (both halves end up with full sum)
        acc0 += __shfl_xor_sync(0xffffffffu, acc0, 16);
        acc1 += __shfl_xor_sync(0xffffffffu, acc1, 16);
        acc2 += __shfl_xor_sync(0xffffffffu, acc2, 16);
        acc3 += __shfl_xor_sync(0xffffffffu, acc3, 16);
#pragma unroll
        for (int o = 16; o > 0; o >>= 1)
            cw += __shfl_xor_sync(0xffffffffu, cw, o);

        float inv = 1.f / fmaxf(cw, 1e-12f);
        float ag0 = acc0 * inv, ag1 = acc1 * inv, ag2 = acc2 * inv, ag3 = acc3 * inv;

        float4 hv = hin4[nd * 16 + q];   // lane q holds h feats [4q..4q+3]

        // node MLP: out[lane], out[lane+32]
        float o0 = nbs[lane];
        float o1 = nbs[lane + 32];
#pragma unroll
        for (int qq = 0; qq < 16; qq++) {
            float bh0 = __shfl_sync(0xffffffffu, hv.x, qq);
            float bh1 = __shfl_sync(0xffffffffu, hv.y, qq);
            float bh2 = __shfl_sync(0xffffffffu, hv.z, qq);
            float bh3 = __shfl_sync(0xffffffffu, hv.w, qq);
            float ba0 = __shfl_sync(0xffffffffu, ag0, qq);
            float ba1 = __shfl_sync(0xffffffffu, ag1, qq);
            float ba2 = __shfl_sync(0xffffffffu, ag2, qq);
            float ba3 = __shfl_sync(0xffffffffu, ag3, qq);
            int k = 4 * qq;
            o0 = fmaf(bh0, Ws[(k + 0) * HH + lane], o0);
            o1 = fmaf(bh0, Ws[(k + 0) * HH + 32 + lane], o1);
            o0 = fmaf(bh1, Ws[(k + 1) * HH + lane], o0);
            o1 = fmaf(bh1, Ws[(k + 1) * HH + 32 + lane], o1);
            o0 = fmaf(bh2, Ws[(k + 2) * HH + lane], o0);
            o1 = fmaf(bh2, Ws[(k + 2) * HH + 32 + lane], o1);
            o0 = fmaf(bh3, Ws[(k + 3) * HH + lane], o0);
            o1 = fmaf(bh3, Ws[(k + 3) * HH + 32 + lane], o1);
            o0 = fmaf(ba0, Ws[(HH + k + 0) * HH + lane], o0);
            o1 = fmaf(ba0, Ws[(HH + k + 0) * HH + 32 + lane], o1);
            o0 = fmaf(ba1, Ws[(HH + k + 1) * HH + lane], o0);
            o1 = fmaf(ba1, Ws[(HH + k + 1) * HH + 32 + lane], o1);
            o0 = fmaf(ba2, Ws[(HH + k + 2) * HH + lane], o0);
            o1 = fmaf(ba2, Ws[(HH + k + 2) * HH + 32 + lane], o1);
            o0 = fmaf(ba3, Ws[(HH + k + 3) * HH + lane], o0);
            o1 = fmaf(ba3, Ws[(HH + k + 3) * HH + 32 + lane], o1);
        }

        float hl = hin[nd * HH + lane];
        float hh = hin[nd * HH + 32 + lane];
        float v0 = hl + fmaxf(o0, 0.f);
        float v1 = hh + fmaxf(o1, 0.f);

        // LayerNorm over 64 features (2 per lane)
        float s1 = v0 + v1;
#pragma unroll
        for (int o = 16; o > 0; o >>= 1)
            s1 += __shfl_xor_sync(0xffffffffu, s1, o);
        float mu = s1 * (1.f / HH);
        float t0 = v0 - mu, t1 = v1 - mu;
        float s2 = t0 * t0 + t1 * t1;
#pragma unroll
        for (int o = 16; o > 0; o >>= 1)
            s2 += __shfl_xor_sync(0xffffffffu, s2, o);
        float var = s2 * (1.f / HH);
        float r = rsqrtf(var + 1e-5f);

        hout[nd * HH + lane]      = t0 * r * gs[lane]      + bs[lane];
        hout[nd * HH + 32 + lane] = t1 * r * gs[lane + 32] + bs[lane + 32];
    }
}

// ---------------------------------------------------------------------------
// Head: out = relu(h @ hw1 + hb1) @ hw2 + hb2
// ---------------------------------------------------------------------------
__global__ void head_kernel(const float* __restrict__ hsrc,
                            const float* __restrict__ hw1,
                            const float* __restrict__ hb1,
                            const float* __restrict__ hw2,
                            const float* __restrict__ hb2,
                            float* __restrict__ out) {
    __shared__ float W1[HH * 32];
    __shared__ float b1s[32], w2s[32];
    for (int i = threadIdx.x; i < HH * 32; i += blockDim.x) W1[i] = hw1[i];
    if (threadIdx.x < 32) {
        b1s[threadIdx.x] = hb1[threadIdx.x];
        w2s[threadIdx.x] = hw2[threadIdx.x];
    }
    __syncthreads();

    int lane = threadIdx.x & 31;
    int warp = threadIdx.x >> 5;
    float bb2 = hb2[0];

    for (int node = blockIdx.x * 8 + warp; node < NN; node += gridDim.x * 8) {
        float hlo = hsrc[node * HH + lane];
        float hhi = hsrc[node * HH + 32 + lane];
        float acc = b1s[lane];
#pragma unroll
        for (int k = 0; k < 32; k++) {
            float hk = __shfl_sync(0xffffffffu, hlo, k);
            acc = fmaf(hk, W1[k * 32 + lane], acc);
        }
#pragma unroll
        for (int k = 0; k < 32; k++) {
            float hk = __shfl_sync(0xffffffffu, hhi, k);
            acc = fmaf(hk, W1[(32 + k) * 32 + lane], acc);
        }
        float p = fmaxf(acc, 0.f) * w2s[lane];
#pragma unroll
        for (int o = 16; o > 0; o >>= 1)
            p += __shfl_xor_sync(0xffffffffu, p, o);
        if (lane == 0) out[node] = p + bb2;
    }
}

// ---------------------------------------------------------------------------
extern "C" void kernel_launch(void* const* d_in, const int* in_sizes, int n_in,
                              void* d_out, int out_size) {
    const float* x   = (const float*)d_in[0];
    const int*   ei  = (const int*)  d_in[1];
    const float* ea  = (const float*)d_in[2];
    const float* Wp  = (const float*)d_in[3];
    const float* bp  = (const float*)d_in[4];
    const float* ew1 = (const float*)d_in[5];
    const float* eb1 = (const float*)d_in[6];
    const float* ew2 = (const float*)d_in[7];
    const float* eb2 = (const float*)d_in[8];
    const float* nw  = (const float*)d_in[9];
    const float* nb  = (const float*)d_in[10];
    const float* lng = (const float*)d_in[11];
    const float* lnb = (const float*)d_in[12];
    const float* hw1 = (const float*)d_in[13];
    const float* hb1 = (const float*)d_in[14];
    const float* hw2 = (const float*)d_in[15];
    const float* hb2 = (const float*)d_in[16];
    float* out = (float*)d_out;

    void* degPtr = nullptr;
    cudaGetSymbolAddress(&degPtr, d_deg);

    float* hA = nullptr; float* hB = nullptr; float* ewp = nullptr;
    cudaGetSymbolAddress((void**)&hA, d_hA);
    cudaGetSymbolAddress((void**)&hB, d_hB);
    cudaGetSymbolAddress((void**)&ewp, d_ew);

    // independent preprocessing
    proj_kernel<<<(NN * HH + 255) / 256, 256>>>(x, Wp, bp);
    gate_kernel<<<EE / 256, 256>>>(ea, ew1, eb1, ew2, eb2);

    cudaMemsetAsync(degPtr, 0, (size_t)NN * sizeof(int));
    count_kernel<<<(EE + 255) / 256, 256>>>(ei);
    scan_kernel<<<1, 1024>>>();
    fill_kernel<<<(EE + 255) / 256, 256>>>(ei);

    // layers: l0 A->B, l1 B->A, l2 A->B
    for (int l = 0; l < LL; l++) {
        const float* hin  = (l & 1) ? hB : hA;
        float*       hout = (l & 1) ? hA : hB;
        layer_kernel<<<592, 256>>>((const float4*)hin, hin, hout,
                                   ewp + (size_t)l * EE,
                                   nw + l * 2 * HH * HH, nb + l * HH,
                                   lng + l * HH, lnb + l * HH);
    }

    head_kernel<<<592, 256>>>(hB, hw1, hb1, hw2, hb2, out);
}

// round 5
// speedup vs baseline: 1.7869x; 1.3730x over previous
#include <cuda_runtime.h>
#include <math.h>

#define NN 50000
#define EE 800000
#define FIN 10
#define HH 64
#define LL 3

__device__ float d_hA[NN * HH];
__device__ float d_hB[NN * HH];
__device__ int   d_deg[NN];
__device__ int   d_off[NN + 1];
__device__ int   d_cur[NN];
__device__ int   d_part[64];
__device__ int   d_base[64];
__device__ int   d_srcp[EE];           // src node per CSR slot
__device__ int   d_perm[EE];           // original edge id per CSR slot
__device__ float d_gcsr[LL * EE];      // gates in CSR order, per layer

// ---------------------------------------------------------------------------
// h = relu(x @ Wp + bp)
// ---------------------------------------------------------------------------
__global__ void proj_kernel(const float* __restrict__ x,
                            const float* __restrict__ Wp,
                            const float* __restrict__ bp) {
    __shared__ float Ws[FIN * HH];
    __shared__ float bs[HH];
    for (int i = threadIdx.x; i < FIN * HH; i += blockDim.x) Ws[i] = Wp[i];
    if (threadIdx.x < HH) bs[threadIdx.x] = bp[threadIdx.x];
    __syncthreads();

    int idx = blockIdx.x * blockDim.x + threadIdx.x;
    if (idx >= NN * HH) return;
    int i = idx >> 6;
    int j = idx & 63;
    float acc = bs[j];
#pragma unroll
    for (int k = 0; k < FIN; k++) acc = fmaf(x[i * FIN + k], Ws[k * HH + j], acc);
    d_hA[idx] = fmaxf(acc, 0.f);
}

// ---------------------------------------------------------------------------
// CSR build: count -> partial sums -> base scan -> block scans -> fill
// ---------------------------------------------------------------------------
__global__ void count_kernel(const int* __restrict__ ei) {
    int e = blockIdx.x * blockDim.x + threadIdx.x;
    if (e >= EE) return;
    atomicAdd(&d_deg[ei[EE + e]], 1);
}

__global__ void partial_kernel() {      // 49 blocks x 1024
    __shared__ int sm[1024];
    int t = threadIdx.x;
    int idx = blockIdx.x * 1024 + t;
    sm[t] = (idx < NN) ? d_deg[idx] : 0;
    __syncthreads();
#pragma unroll
    for (int o = 512; o > 0; o >>= 1) {
        if (t < o) sm[t] += sm[t + o];
        __syncthreads();
    }
    if (t == 0) d_part[blockIdx.x] = sm[0];
}

__global__ void base_kernel() {         // 1 block x 64
    __shared__ int sm[64];
    int t = threadIdx.x;
    int v = (t < 49) ? d_part[t] : 0;
    sm[t] = v;
    __syncthreads();
#pragma unroll
    for (int o = 1; o < 64; o <<= 1) {
        int u = (t >= o) ? sm[t - o] : 0;
        __syncthreads();
        sm[t] += u;
        __syncthreads();
    }
    if (t < 49) d_base[t] = sm[t] - v;
    if (t == 48) d_off[NN] = sm[48];
}

__global__ void offs_kernel() {         // 49 blocks x 1024
    __shared__ int sm[1024];
    int t = threadIdx.x;
    int idx = blockIdx.x * 1024 + t;
    int v = (idx < NN) ? d_deg[idx] : 0;
    sm[t] = v;
    __syncthreads();
#pragma unroll
    for (int o = 1; o < 1024; o <<= 1) {
        int u = (t >= o) ? sm[t - o] : 0;
        __syncthreads();
        sm[t] += u;
        __syncthreads();
    }
    if (idx < NN) {
        int excl = sm[t] - v + d_base[blockIdx.x];
        d_off[idx] = excl;
        d_cur[idx] = excl;
    }
}

__global__ void fill_kernel(const int* __restrict__ ei) {
    int e = blockIdx.x * blockDim.x + threadIdx.x;
    if (e >= EE) return;
    int s = ei[e];
    int d = ei[EE + e];
    int p = atomicAdd(&d_cur[d], 1);
    d_srcp[p] = s;
    d_perm[p] = e;
}

// ---------------------------------------------------------------------------
// Gates for all 3 layers, written directly in CSR order.
// ---------------------------------------------------------------------------
__global__ void gatecsr_kernel(const float* __restrict__ ea,
                               const float* __restrict__ ew1,
                               const float* __restrict__ eb1,
                               const float* __restrict__ ew2,
                               const float* __restrict__ eb2) {
    __shared__ float W1[LL * 3 * 16];
    __shared__ float B1[LL * 16];
    __shared__ float W2[LL * 16];
    __shared__ float B2[LL];
    for (int i = threadIdx.x; i < LL * 3 * 16; i += blockDim.x) W1[i] = ew1[i];
    if (threadIdx.x < LL * 16) {
        B1[threadIdx.x] = eb1[threadIdx.x];
        W2[threadIdx.x] = ew2[threadIdx.x];
    }
    if (threadIdx.x < LL) B2[threadIdx.x] = eb2[threadIdx.x];
    __syncthreads();

    int p = blockIdx.x * blockDim.x + threadIdx.x;   // EE % 256 == 0
    int e = d_perm[p];
    float a0 = ea[e * 3 + 0];
    float a1 = ea[e * 3 + 1];
    float a2 = ea[e * 3 + 2];
#pragma unroll
    for (int l = 0; l < LL; l++) {
        float z = B2[l];
#pragma unroll
        for (int k = 0; k < 16; k++) {
            float hk = B1[l * 16 + k];
            hk = fmaf(a0, W1[l * 48 + 0 * 16 + k], hk);
            hk = fmaf(a1, W1[l * 48 + 1 * 16 + k], hk);
            hk = fmaf(a2, W1[l * 48 + 2 * 16 + k], hk);
            z = fmaf(fmaxf(hk, 0.f), W2[l * 16 + k], z);
        }
        d_gcsr[l * EE + p] = 1.f / (1.f + __expf(-z));
    }
}

// ---------------------------------------------------------------------------
// Fused layer: warp per dst node. CSR gather -> agg in regs -> stage [h,agg]
// in smem -> MLP with transposed weights (LDS.128 rows) -> residual + LN.
// ---------------------------------------------------------------------------
#define WPAD 132   // padded row stride (floats) for transposed weights

__global__ void __launch_bounds__(256)
layer_kernel(const float4* __restrict__ hin4,
             float* __restrict__ hout,
             const float* __restrict__ gcsr_l,
             const float* __restrict__ nw,
             const float* __restrict__ nb,
             const float* __restrict__ g,
             const float* __restrict__ b) {
    __shared__ float Ws[HH * WPAD];        // WsT[j][k] = nw[k][j], padded
    __shared__ float nbs[HH], gs[HH], bs[HH];
    __shared__ float ins[8][2 * HH];       // per-warp staged [h, agg]

    for (int i = threadIdx.x; i < 2 * HH * HH; i += blockDim.x) {
        int k = i >> 6;        // 0..127
        int j = i & 63;        // 0..63
        Ws[j * WPAD + k] = nw[i];
    }
    if (threadIdx.x < HH) {
        nbs[threadIdx.x] = nb[threadIdx.x];
        gs[threadIdx.x]  = g[threadIdx.x];
        bs[threadIdx.x]  = b[threadIdx.x];
    }
    __syncthreads();

    int warp = threadIdx.x >> 5;
    int lane = threadIdx.x & 31;
    int q    = lane & 15;
    int half = lane >> 4;

    const float4* row0 = (const float4*)&Ws[lane * WPAD];          // out feat lane
    const float4* row1 = (const float4*)&Ws[(lane + 32) * WPAD];   // out feat lane+32
    float4* ins4 = (float4*)&ins[warp][0];

    for (int nd = blockIdx.x * 8 + warp; nd < NN; nd += gridDim.x * 8) {
        int e0 = d_off[nd];
        int e1 = d_off[nd + 1];

        float acc0 = 0.f, acc1 = 0.f, acc2 = 0.f, acc3 = 0.f;
        float cw = 0.f;

        for (int base = e0; base < e1; base += 32) {
            int n = e1 - base;
            if (n > 32) n = 32;
            int   s = 0;
            float w = 0.f;
            if (lane < n) {
                s = d_srcp[base + lane];
                w = gcsr_l[base + lane];
            }
            cw += w;
            for (int i = 0; i < n; i += 2) {
                int idx = i + half;
                int   si = __shfl_sync(0xffffffffu, s, idx);
                float wi = __shfl_sync(0xffffffffu, w, idx);
                if (idx < n) {
                    float4 v = hin4[si * 16 + q];
                    acc0 = fmaf(v.x, wi, acc0);
                    acc1 = fmaf(v.y, wi, acc1);
                    acc2 = fmaf(v.z, wi, acc2);
                    acc3 = fmaf(v.w, wi, acc3);
                }
            }
        }
        acc0 += __shfl_xor_sync(0xffffffffu, acc0, 16);
        acc1 += __shfl_xor_sync(0xffffffffu, acc1, 16);
        acc2 += __shfl_xor_sync(0xffffffffu, acc2, 16);
        acc3 += __shfl_xor_sync(0xffffffffu, acc3, 16);
#pragma unroll
        for (int o = 16; o > 0; o >>= 1)
            cw += __shfl_xor_sync(0xffffffffu, cw, o);

        float inv = 1.f / fmaxf(cw, 1e-12f);
        float4 hv = hin4[nd * 16 + q];

        if (lane < 16) {
            ins4[q] = hv;
            ins4[16 + q] = make_float4(acc0 * inv, acc1 * inv, acc2 * inv, acc3 * inv);
        }
        __syncwarp();

        // MLP: o0 = out[lane], o1 = out[lane+32]
        float o0 = nbs[lane];
        float o1 = nbs[lane + 32];
#pragma unroll
        for (int qq = 0; qq < 16; qq++) {
            float4 xh = ins4[qq];
            float4 xa = ins4[16 + qq];
            float4 wh0 = row0[qq];
            float4 wa0 = row0[16 + qq];
            float4 wh1 = row1[qq];
            float4 wa1 = row1[16 + qq];
            o0 = fmaf(xh.x, wh0.x, o0); o0 = fmaf(xh.y, wh0.y, o0);
            o0 = fmaf(xh.z, wh0.z, o0); o0 = fmaf(xh.w, wh0.w, o0);
            o0 = fmaf(xa.x, wa0.x, o0); o0 = fmaf(xa.y, wa0.y, o0);
            o0 = fmaf(xa.z, wa0.z, o0); o0 = fmaf(xa.w, wa0.w, o0);
            o1 = fmaf(xh.x, wh1.x, o1); o1 = fmaf(xh.y, wh1.y, o1);
            o1 = fmaf(xh.z, wh1.z, o1); o1 = fmaf(xh.w, wh1.w, o1);
            o1 = fmaf(xa.x, wa1.x, o1); o1 = fmaf(xa.y, wa1.y, o1);
            o1 = fmaf(xa.z, wa1.z, o1); o1 = fmaf(xa.w, wa1.w, o1);
        }

        float hl = ins[warp][lane];
        float hh = ins[warp][32 + lane];
        float v0 = hl + fmaxf(o0, 0.f);
        float v1 = hh + fmaxf(o1, 0.f);

        float s1 = v0 + v1;
#pragma unroll
        for (int o = 16; o > 0; o >>= 1)
            s1 += __shfl_xor_sync(0xffffffffu, s1, o);
        float mu = s1 * (1.f / HH);
        float t0 = v0 - mu, t1 = v1 - mu;
        float s2 = t0 * t0 + t1 * t1;
#pragma unroll
        for (int o = 16; o > 0; o >>= 1)
            s2 += __shfl_xor_sync(0xffffffffu, s2, o);
        float var = s2 * (1.f / HH);
        float r = rsqrtf(var + 1e-5f);

        hout[nd * HH + lane]      = t0 * r * gs[lane]      + bs[lane];
        hout[nd * HH + 32 + lane] = t1 * r * gs[lane + 32] + bs[lane + 32];
        __syncwarp();
    }
}

// ---------------------------------------------------------------------------
// Head: out = relu(h @ hw1 + hb1) @ hw2 + hb2
// ---------------------------------------------------------------------------
__global__ void head_kernel(const float* __restrict__ hsrc,
                            const float* __restrict__ hw1,
                            const float* __restrict__ hb1,
                            const float* __restrict__ hw2,
                            const float* __restrict__ hb2,
                            float* __restrict__ out) {
    __shared__ float W1[HH * 32];
    __shared__ float b1s[32], w2s[32];
    for (int i = threadIdx.x; i < HH * 32; i += blockDim.x) W1[i] = hw1[i];
    if (threadIdx.x < 32) {
        b1s[threadIdx.x] = hb1[threadIdx.x];
        w2s[threadIdx.x] = hw2[threadIdx.x];
    }
    __syncthreads();

    int lane = threadIdx.x & 31;
    int warp = threadIdx.x >> 5;
    float bb2 = hb2[0];

    for (int node = blockIdx.x * 8 + warp; node < NN; node += gridDim.x * 8) {
        float hlo = hsrc[node * HH + lane];
        float hhi = hsrc[node * HH + 32 + lane];
        float acc = b1s[lane];
#pragma unroll
        for (int k = 0; k < 32; k++) {
            float hk = __shfl_sync(0xffffffffu, hlo, k);
            acc = fmaf(hk, W1[k * 32 + lane], acc);
        }
#pragma unroll
        for (int k = 0; k < 32; k++) {
            float hk = __shfl_sync(0xffffffffu, hhi, k);
            acc = fmaf(hk, W1[(32 + k) * 32 + lane], acc);
        }
        float p = fmaxf(acc, 0.f) * w2s[lane];
#pragma unroll
        for (int o = 16; o > 0; o >>= 1)
            p += __shfl_xor_sync(0xffffffffu, p, o);
        if (lane == 0) out[node] = p + bb2;
    }
}

// ---------------------------------------------------------------------------
extern "C" void kernel_launch(void* const* d_in, const int* in_sizes, int n_in,
                              void* d_out, int out_size) {
    const float* x   = (const float*)d_in[0];
    const int*   ei  = (const int*)  d_in[1];
    const float* ea  = (const float*)d_in[2];
    const float* Wp  = (const float*)d_in[3];
    const float* bp  = (const float*)d_in[4];
    const float* ew1 = (const float*)d_in[5];
    const float* eb1 = (const float*)d_in[6];
    const float* ew2 = (const float*)d_in[7];
    const float* eb2 = (const float*)d_in[8];
    const float* nw  = (const float*)d_in[9];
    const float* nb  = (const float*)d_in[10];
    const float* lng = (const float*)d_in[11];
    const float* lnb = (const float*)d_in[12];
    const float* hw1 = (const float*)d_in[13];
    const float* hb1 = (const float*)d_in[14];
    const float* hw2 = (const float*)d_in[15];
    const float* hb2 = (const float*)d_in[16];
    float* out = (float*)d_out;

    void* degPtr = nullptr;
    cudaGetSymbolAddress(&degPtr, d_deg);
    float* hA = nullptr; float* hB = nullptr; float* gcsr = nullptr;
    cudaGetSymbolAddress((void**)&hA, d_hA);
    cudaGetSymbolAddress((void**)&hB, d_hB);
    cudaGetSymbolAddress((void**)&gcsr, d_gcsr);

    proj_kernel<<<(NN * HH + 255) / 256, 256>>>(x, Wp, bp);

    cudaMemsetAsync(degPtr, 0, (size_t)NN * sizeof(int));
    count_kernel<<<(EE + 255) / 256, 256>>>(ei);
    partial_kernel<<<49, 1024>>>();
    base_kernel<<<1, 64>>>();
    offs_kernel<<<49, 1024>>>();
    fill_kernel<<<(EE + 255) / 256, 256>>>(ei);
    gatecsr_kernel<<<EE / 256, 256>>>(ea, ew1, eb1, ew2, eb2);

    for (int l = 0; l < LL; l++) {
        const float* hin  = (l & 1) ? hB : hA;
        float*       hout = (l & 1) ? hA : hB;
        layer_kernel<<<592, 256>>>((const float4*)hin, hout,
                                   gcsr + (size_t)l * EE,
                                   nw + l * 2 * HH * HH, nb + l * HH,
                                   lng + l * HH, lnb + l * HH);
    }

    head_kernel<<<592, 256>>>(hB, hw1, hb1, hw2, hb2, out);
}

// round 7
// speedup vs baseline: 2.2380x; 1.2525x over previous
#include <cuda_runtime.h>
#include <math.h>
#include <stdint.h>

#define NN 50000
#define EE 800000
#define FIN 10
#define HH 64
#define LL 3

__device__ float d_hA[NN * HH];
__device__ float d_hB[NN * HH];
__device__ int   d_deg[NN];
__device__ int   d_off[NN + 1];
__device__ int   d_cur[NN];
__device__ int   d_part[64];
__device__ int   d_base[64];
__device__ int   d_srcp[EE];           // src node per CSR slot
__device__ int   d_perm[EE];           // original edge id per CSR slot
__device__ float d_gcsr[LL * EE];      // gates in CSR order, per layer

// ---------------------------------------------------------------------------
// packed f32x2 helpers
// ---------------------------------------------------------------------------
__device__ __forceinline__ void ldsv2u64(uint32_t addr,
                                         unsigned long long& a,
                                         unsigned long long& b) {
    asm volatile("ld.shared.v2.u64 {%0,%1}, [%2];"
                 : "=l"(a), "=l"(b) : "r"(addr));
}
__device__ __forceinline__ void ffma2(unsigned long long& d,
                                      unsigned long long a,
                                      unsigned long long b) {
    asm("fma.rn.f32x2 %0, %1, %2, %0;" : "+l"(d) : "l"(a), "l"(b));
}
__device__ __forceinline__ float pairsum(unsigned long long v) {
    uint32_t lo, hi;
    asm("mov.b64 {%0,%1}, %2;" : "=r"(lo), "=r"(hi) : "l"(v));
    return __uint_as_float(lo) + __uint_as_float(hi);
}

// ---------------------------------------------------------------------------
// h = relu(x @ Wp + bp)
// ---------------------------------------------------------------------------
__global__ void proj_kernel(const float* __restrict__ x,
                            const float* __restrict__ Wp,
                            const float* __restrict__ bp) {
    __shared__ float Ws[FIN * HH];
    __shared__ float bs[HH];
    for (int i = threadIdx.x; i < FIN * HH; i += blockDim.x) Ws[i] = Wp[i];
    if (threadIdx.x < HH) bs[threadIdx.x] = bp[threadIdx.x];
    __syncthreads();

    int idx = blockIdx.x * blockDim.x + threadIdx.x;
    if (idx >= NN * HH) return;
    int i = idx >> 6;
    int j = idx & 63;
    float acc = bs[j];
#pragma unroll
    for (int k = 0; k < FIN; k++) acc = fmaf(x[i * FIN + k], Ws[k * HH + j], acc);
    d_hA[idx] = fmaxf(acc, 0.f);
}

// ---------------------------------------------------------------------------
// CSR build: count -> partial sums -> base scan -> block scans -> fill
// ---------------------------------------------------------------------------
__global__ void count_kernel(const int* __restrict__ ei) {
    int e = blockIdx.x * blockDim.x + threadIdx.x;
    if (e >= EE) return;
    atomicAdd(&d_deg[ei[EE + e]], 1);
}

__global__ void partial_kernel() {      // 49 blocks x 1024
    __shared__ int sm[1024];
    int t = threadIdx.x;
    int idx = blockIdx.x * 1024 + t;
    sm[t] = (idx < NN) ? d_deg[idx] : 0;
    __syncthreads();
#pragma unroll
    for (int o = 512; o > 0; o >>= 1) {
        if (t < o) sm[t] += sm[t + o];
        __syncthreads();
    }
    if (t == 0) d_part[blockIdx.x] = sm[0];
}

__global__ void base_kernel() {         // 1 block x 64
    __shared__ int sm[64];
    int t = threadIdx.x;
    int v = (t < 49) ? d_part[t] : 0;
    sm[t] = v;
    __syncthreads();
#pragma unroll
    for (int o = 1; o < 64; o <<= 1) {
        int u = (t >= o) ? sm[t - o] : 0;
        __syncthreads();
        sm[t] += u;
        __syncthreads();
    }
    if (t < 49) d_base[t] = sm[t] - v;
    if (t == 48) d_off[NN] = sm[48];
}

__global__ void offs_kernel() {         // 49 blocks x 1024
    __shared__ int sm[1024];
    int t = threadIdx.x;
    int idx = blockIdx.x * 1024 + t;
    int v = (idx < NN) ? d_deg[idx] : 0;
    sm[t] = v;
    __syncthreads();
#pragma unroll
    for (int o = 1; o < 1024; o <<= 1) {
        int u = (t >= o) ? sm[t - o] : 0;
        __syncthreads();
        sm[t] += u;
        __syncthreads();
    }
    if (idx < NN) {
        int excl = sm[t] - v + d_base[blockIdx.x];
        d_off[idx] = excl;
        d_cur[idx] = excl;
    }
}

__global__ void fill_kernel(const int* __restrict__ ei) {
    int e = blockIdx.x * blockDim.x + threadIdx.x;
    if (e >= EE) return;
    int s = ei[e];
    int d = ei[EE + e];
    int p = atomicAdd(&d_cur[d], 1);
    d_srcp[p] = s;
    d_perm[p] = e;
}

// ---------------------------------------------------------------------------
// Gates for all 3 layers, written directly in CSR order.
// ---------------------------------------------------------------------------
__global__ void gatecsr_kernel(const float* __restrict__ ea,
                               const float* __restrict__ ew1,
                               const float* __restrict__ eb1,
                               const float* __restrict__ ew2,
                               const float* __restrict__ eb2) {
    __shared__ float W1[LL * 3 * 16];
    __shared__ float B1[LL * 16];
    __shared__ float W2[LL * 16];
    __shared__ float B2[LL];
    for (int i = threadIdx.x; i < LL * 3 * 16; i += blockDim.x) W1[i] = ew1[i];
    if (threadIdx.x < LL * 16) {
        B1[threadIdx.x] = eb1[threadIdx.x];
        W2[threadIdx.x] = ew2[threadIdx.x];
    }
    if (threadIdx.x < LL) B2[threadIdx.x] = eb2[threadIdx.x];
    __syncthreads();

    int p = blockIdx.x * blockDim.x + threadIdx.x;   // EE % 256 == 0
    int e = d_perm[p];
    float a0 = ea[e * 3 + 0];
    float a1 = ea[e * 3 + 1];
    float a2 = ea[e * 3 + 2];
#pragma unroll
    for (int l = 0; l < LL; l++) {
        float z = B2[l];
#pragma unroll
        for (int k = 0; k < 16; k++) {
            float hk = B1[l * 16 + k];
            hk = fmaf(a0, W1[l * 48 + 0 * 16 + k], hk);
            hk = fmaf(a1, W1[l * 48 + 1 * 16 + k], hk);
            hk = fmaf(a2, W1[l * 48 + 2 * 16 + k], hk);
            z = fmaf(fmaxf(hk, 0.f), W2[l * 16 + k], z);
        }
        d_gcsr[l * EE + p] = 1.f / (1.f + __expf(-z));
    }
}

// ---------------------------------------------------------------------------
// Fused layer: warp per 4 dst nodes.
//   Phase A (per node): CSR gather of ew-weighted h[src] into registers,
//   staged with h into per-warp smem (ins).
//   Phase B: joint 128->64 MLP for all 4 nodes; weights in k-interleaved
//   float4 layout, FFMA2 (fma.rn.f32x2) with v2.u64 smem loads.
//   Phase C (per node): residual + LayerNorm, write hout.
// ---------------------------------------------------------------------------
__global__ void __launch_bounds__(256)
layer_kernel(const float4* __restrict__ hin4,
             float* __restrict__ hout,
             const float* __restrict__ gcsr_l,
             const float* __restrict__ nw,
             const float* __restrict__ nb,
             const float* __restrict__ g,
             const float* __restrict__ b) {
    // Wq[t][j] (t=k/4 in 0..31, j in 0..63) float4 = (nw[4t][j],nw[4t+1][j],nw[4t+2][j],nw[4t+3][j])
    __shared__ float4 Wq[32 * 64];         // 32 KB
    __shared__ float nbs[HH], gs[HH], bs[HH];
    __shared__ float ins[8][4 * 2 * HH];   // per-warp, 4 nodes x [h(64),agg(64)]

    {
        float* Wqf = (float*)Wq;
        for (int i = threadIdx.x; i < 2 * HH * HH; i += blockDim.x) {
            int k = i >> 6;        // 0..127
            int j = i & 63;        // 0..63
            Wqf[((k >> 2) * 64 + j) * 4 + (k & 3)] = nw[i];
        }
    }
    if (threadIdx.x < HH) {
        nbs[threadIdx.x] = nb[threadIdx.x];
        gs[threadIdx.x]  = g[threadIdx.x];
        bs[threadIdx.x]  = b[threadIdx.x];
    }
    __syncthreads();

    int warp = threadIdx.x >> 5;
    int lane = threadIdx.x & 31;
    int q    = lane & 15;
    int half = lane >> 4;

    float* insw = &ins[warp][0];
    float4* ins4 = (float4*)insw;
    uint32_t insAddr = (uint32_t)__cvta_generic_to_shared(insw);
    uint32_t wBase   = (uint32_t)__cvta_generic_to_shared(Wq) + lane * 16;

    for (int nd0 = (blockIdx.x * 8 + warp) * 4; nd0 < NN; nd0 += gridDim.x * 32) {
        // ---- Phase A: gather 4 nodes ----
#pragma unroll
        for (int nloc = 0; nloc < 4; nloc++) {
            int nd = nd0 + nloc;
            int e0 = d_off[nd];
            int e1 = d_off[nd + 1];

            float acc0 = 0.f, acc1 = 0.f, acc2 = 0.f, acc3 = 0.f;
            float cw = 0.f;

            for (int base = e0; base < e1; base += 32) {
                int n = e1 - base;
                if (n > 32) n = 32;
                int   s = 0;
                float w = 0.f;
                if (lane < n) {
                    s = d_srcp[base + lane];
                    w = gcsr_l[base + lane];
                }
                cw += w;
                for (int i = 0; i < n; i += 2) {
                    int idx = i + half;
                    int   si = __shfl_sync(0xffffffffu, s, idx);
                    float wi = __shfl_sync(0xffffffffu, w, idx);
                    if (idx < n) {
                        float4 v = hin4[si * 16 + q];
                        acc0 = fmaf(v.x, wi, acc0);
                        acc1 = fmaf(v.y, wi, acc1);
                        acc2 = fmaf(v.z, wi, acc2);
                        acc3 = fmaf(v.w, wi, acc3);
                    }
                }
            }
            acc0 += __shfl_xor_sync(0xffffffffu, acc0, 16);
            acc1 += __shfl_xor_sync(0xffffffffu, acc1, 16);
            acc2 += __shfl_xor_sync(0xffffffffu, acc2, 16);
            acc3 += __shfl_xor_sync(0xffffffffu, acc3, 16);
#pragma unroll
            for (int o = 16; o > 0; o >>= 1)
                cw += __shfl_xor_sync(0xffffffffu, cw, o);

            float inv = 1.f / fmaxf(cw, 1e-12f);
            if (lane < 16) {
                ins4[nloc * 32 + q]      = hin4[(size_t)nd * 16 + q];
                ins4[nloc * 32 + 16 + q] =
                    make_float4(acc0 * inv, acc1 * inv, acc2 * inv, acc3 * inv);
            }
            __syncwarp();
        }

        // ---- Phase B: joint MLP (FFMA2) ----
        unsigned long long aA0 = 0, aA1 = 0, aA2 = 0, aA3 = 0;  // out feat = lane
        unsigned long long aB0 = 0, aB1 = 0, aB2 = 0, aB3 = 0;  // out feat = lane+32
        uint32_t wAddr = wBase;
#pragma unroll
        for (int t = 0; t < 32; t++) {
            unsigned long long wa0, wa1, wb0, wb1;
            ldsv2u64(wAddr, wa0, wa1);          // j = lane,    k = 4t..4t+3
            ldsv2u64(wAddr + 512, wb0, wb1);    // j = lane+32
            unsigned long long x0, x1;
            ldsv2u64(insAddr + 0 * 512 + t * 16, x0, x1);
            ffma2(aA0, x0, wa0); ffma2(aA0, x1, wa1);
            ffma2(aB0, x0, wb0); ffma2(aB0, x1, wb1);
            ldsv2u64(insAddr + 1 * 512 + t * 16, x0, x1);
            ffma2(aA1, x0, wa0); ffma2(aA1, x1, wa1);
            ffma2(aB1, x0, wb0); ffma2(aB1, x1, wb1);
            ldsv2u64(insAddr + 2 * 512 + t * 16, x0, x1);
            ffma2(aA2, x0, wa0); ffma2(aA2, x1, wa1);
            ffma2(aB2, x0, wb0); ffma2(aB2, x1, wb1);
            ldsv2u64(insAddr + 3 * 512 + t * 16, x0, x1);
            ffma2(aA3, x0, wa0); ffma2(aA3, x1, wa1);
            ffma2(aB3, x0, wb0); ffma2(aB3, x1, wb1);
            wAddr += 1024;
        }

        float o0n[4], o1n[4];
        o0n[0] = pairsum(aA0); o0n[1] = pairsum(aA1);
        o0n[2] = pairsum(aA2); o0n[3] = pairsum(aA3);
        o1n[0] = pairsum(aB0); o1n[1] = pairsum(aB1);
        o1n[2] = pairsum(aB2); o1n[3] = pairsum(aB3);

        float bias0 = nbs[lane];
        float bias1 = nbs[lane + 32];

        // ---- Phase C: residual + LN per node ----
#pragma unroll
        for (int nloc = 0; nloc < 4; nloc++) {
            int nd = nd0 + nloc;
            float hl = insw[nloc * 128 + lane];
            float hh = insw[nloc * 128 + 32 + lane];
            float v0 = hl + fmaxf(o0n[nloc] + bias0, 0.f);
            float v1 = hh + fmaxf(o1n[nloc] + bias1, 0.f);

            float s1 = v0 + v1;
#pragma unroll
            for (int o = 16; o > 0; o >>= 1)
                s1 += __shfl_xor_sync(0xffffffffu, s1, o);
            float mu = s1 * (1.f / HH);
            float t0 = v0 - mu, t1 = v1 - mu;
            float s2 = t0 * t0 + t1 * t1;
#pragma unroll
            for (int o = 16; o > 0; o >>= 1)
                s2 += __shfl_xor_sync(0xffffffffu, s2, o);
            float var = s2 * (1.f / HH);
            float r = rsqrtf(var + 1e-5f);

            hout[nd * HH + lane]      = t0 * r * gs[lane]      + bs[lane];
            hout[nd * HH + 32 + lane] = t1 * r * gs[lane + 32] + bs[lane + 32];
        }
        __syncwarp();
    }
}

// ---------------------------------------------------------------------------
// Head: out = relu(h @ hw1 + hb1) @ hw2 + hb2
// ---------------------------------------------------------------------------
__global__ void head_kernel(const float* __restrict__ hsrc,
                            const float* __restrict__ hw1,
                            const float* __restrict__ hb1,
                            const float* __restrict__ hw2,
                            const float* __restrict__ hb2,
                            float* __restrict__ out) {
    __shared__ float W1[HH * 32];
    __shared__ float b1s[32], w2s[32];
    for (int i = threadIdx.x; i < HH * 32; i += blockDim.x) W1[i] = hw1[i];
    if (threadIdx.x < 32) {
        b1s[threadIdx.x] = hb1[threadIdx.x];
        w2s[threadIdx.x] = hw2[threadIdx.x];
    }
    __syncthreads();

    int lane = threadIdx.x & 31;
    int warp = threadIdx.x >> 5;
    float bb2 = hb2[0];

    for (int node = blockIdx.x * 8 + warp; node < NN; node += gridDim.x * 8) {
        float hlo = hsrc[node * HH + lane];
        float hhi = hsrc[node * HH + 32 + lane];
        float acc = b1s[lane];
#pragma unroll
        for (int k = 0; k < 32; k++) {
            float hk = __shfl_sync(0xffffffffu, hlo, k);
            acc = fmaf(hk, W1[k * 32 + lane], acc);
        }
#pragma unroll
        for (int k = 0; k < 32; k++) {
            float hk = __shfl_sync(0xffffffffu, hhi, k);
            acc = fmaf(hk, W1[(32 + k) * 32 + lane], acc);
        }
        float p = fmaxf(acc, 0.f) * w2s[lane];
#pragma unroll
        for (int o = 16; o > 0; o >>= 1)
            p += __shfl_xor_sync(0xffffffffu, p, o);
        if (lane == 0) out[node] = p + bb2;
    }
}

// ---------------------------------------------------------------------------
extern "C" void kernel_launch(void* const* d_in, const int* in_sizes, int n_in,
                              void* d_out, int out_size) {
    const float* x   = (const float*)d_in[0];
    const int*   ei  = (const int*)  d_in[1];
    const float* ea  = (const float*)d_in[2];
    const float* Wp  = (const float*)d_in[3];
    const float* bp  = (const float*)d_in[4];
    const float* ew1 = (const float*)d_in[5];
    const float* eb1 = (const float*)d_in[6];
    const float* ew2 = (const float*)d_in[7];
    const float* eb2 = (const float*)d_in[8];
    const float* nw  = (const float*)d_in[9];
    const float* nb  = (const float*)d_in[10];
    const float* lng = (const float*)d_in[11];
    const float* lnb = (const float*)d_in[12];
    const float* hw1 = (const float*)d_in[13];
    const float* hb1 = (const float*)d_in[14];
    const float* hw2 = (const float*)d_in[15];
    const float* hb2 = (const float*)d_in[16];
    float* out = (float*)d_out;

    void* degPtr = nullptr;
    cudaGetSymbolAddress(&degPtr, d_deg);
    float* hA = nullptr; float* hB = nullptr; float* gcsr = nullptr;
    cudaGetSymbolAddress((void**)&hA, d_hA);
    cudaGetSymbolAddress((void**)&hB, d_hB);
    cudaGetSymbolAddress((void**)&gcsr, d_gcsr);

    proj_kernel<<<(NN * HH + 255) / 256, 256>>>(x, Wp, bp);

    cudaMemsetAsync(degPtr, 0, (size_t)NN * sizeof(int));
    count_kernel<<<(EE + 255) / 256, 256>>>(ei);
    partial_kernel<<<49, 1024>>>();
    base_kernel<<<1, 64>>>();
    offs_kernel<<<49, 1024>>>();
    fill_kernel<<<(EE + 255) / 256, 256>>>(ei);
    gatecsr_kernel<<<EE / 256, 256>>>(ea, ew1, eb1, ew2, eb2);

    for (int l = 0; l < LL; l++) {
        const float* hin  = (l & 1) ? hB : hA;
        float*       hout = (l & 1) ? hA : hB;
        layer_kernel<<<592, 256>>>((const float4*)hin, hout,
                                   gcsr + (size_t)l * EE,
                                   nw + l * 2 * HH * HH, nb + l * HH,
                                   lng + l * HH, lnb + l * HH);
    }

    head_kernel<<<592, 256>>>(hB, hw1, hb1, hw2, hb2, out);
}

// round 9
// speedup vs baseline: 2.4361x; 1.0885x over previous
#include <cuda_runtime.h>
#include <math.h>
#include <stdint.h>

#define NN 50000
#define EE 800000
#define FIN 10
#define HH 64
#define LL 3

__device__ float d_hA[NN * HH];
__device__ float d_hB[NN * HH];
__device__ int   d_deg[NN];
__device__ int   d_off[NN + 1];
__device__ int   d_cur[NN];
__device__ int   d_part[64];
__device__ int   d_base[64];
__device__ int   d_srcp[EE];           // src node per CSR slot
__device__ int   d_perm[EE];           // original edge id per CSR slot
__device__ float d_gcsr[LL * EE];      // gates in CSR order, per layer

// ---------------------------------------------------------------------------
// packed f32x2 helpers
// ---------------------------------------------------------------------------
__device__ __forceinline__ void ldsv2u64(uint32_t addr,
                                         unsigned long long& a,
                                         unsigned long long& b) {
    asm volatile("ld.shared.v2.u64 {%0,%1}, [%2];"
                 : "=l"(a), "=l"(b) : "r"(addr));
}
__device__ __forceinline__ void ffma2(unsigned long long& d,
                                      unsigned long long a,
                                      unsigned long long b) {
    asm("fma.rn.f32x2 %0, %1, %2, %0;" : "+l"(d) : "l"(a), "l"(b));
}
__device__ __forceinline__ float pairsum(unsigned long long v) {
    uint32_t lo, hi;
    asm("mov.b64 {%0,%1}, %2;" : "=r"(lo), "=r"(hi) : "l"(v));
    return __uint_as_float(lo) + __uint_as_float(hi);
}

// ---------------------------------------------------------------------------
// h = relu(x @ Wp + bp)
// ---------------------------------------------------------------------------
__global__ void proj_kernel(const float* __restrict__ x,
                            const float* __restrict__ Wp,
                            const float* __restrict__ bp) {
    __shared__ float Ws[FIN * HH];
    __shared__ float bs[HH];
    for (int i = threadIdx.x; i < FIN * HH; i += blockDim.x) Ws[i] = Wp[i];
    if (threadIdx.x < HH) bs[threadIdx.x] = bp[threadIdx.x];
    __syncthreads();

    int idx = blockIdx.x * blockDim.x + threadIdx.x;
    if (idx >= NN * HH) return;
    int i = idx >> 6;
    int j = idx & 63;
    float acc = bs[j];
#pragma unroll
    for (int k = 0; k < FIN; k++) acc = fmaf(x[i * FIN + k], Ws[k * HH + j], acc);
    d_hA[idx] = fmaxf(acc, 0.f);
}

// ---------------------------------------------------------------------------
// CSR build: count -> partial sums -> base scan -> block scans -> fill
// ---------------------------------------------------------------------------
__global__ void count_kernel(const int* __restrict__ ei) {
    int e = blockIdx.x * blockDim.x + threadIdx.x;
    if (e >= EE) return;
    atomicAdd(&d_deg[ei[EE + e]], 1);
}

__global__ void partial_kernel() {      // 49 blocks x 1024
    __shared__ int sm[1024];
    int t = threadIdx.x;
    int idx = blockIdx.x * 1024 + t;
    sm[t] = (idx < NN) ? d_deg[idx] : 0;
    __syncthreads();
#pragma unroll
    for (int o = 512; o > 0; o >>= 1) {
        if (t < o) sm[t] += sm[t + o];
        __syncthreads();
    }
    if (t == 0) d_part[blockIdx.x] = sm[0];
}

__global__ void base_kernel() {         // 1 block x 64
    __shared__ int sm[64];
    int t = threadIdx.x;
    int v = (t < 49) ? d_part[t] : 0;
    sm[t] = v;
    __syncthreads();
#pragma unroll
    for (int o = 1; o < 64; o <<= 1) {
        int u = (t >= o) ? sm[t - o] : 0;
        __syncthreads();
        sm[t] += u;
        __syncthreads();
    }
    if (t < 49) d_base[t] = sm[t] - v;
    if (t == 48) d_off[NN] = sm[48];
}

__global__ void offs_kernel() {         // 49 blocks x 1024
    __shared__ int sm[1024];
    int t = threadIdx.x;
    int idx = blockIdx.x * 1024 + t;
    int v = (idx < NN) ? d_deg[idx] : 0;
    sm[t] = v;
    __syncthreads();
#pragma unroll
    for (int o = 1; o < 1024; o <<= 1) {
        int u = (t >= o) ? sm[t - o] : 0;
        __syncthreads();
        sm[t] += u;
        __syncthreads();
    }
    if (idx < NN) {
        int excl = sm[t] - v + d_base[blockIdx.x];
        d_off[idx] = excl;
        d_cur[idx] = excl;
    }
}

__global__ void fill_kernel(const int* __restrict__ ei) {
    int e = blockIdx.x * blockDim.x + threadIdx.x;
    if (e >= EE) return;
    int s = ei[e];
    int d = ei[EE + e];
    int p = atomicAdd(&d_cur[d], 1);
    d_srcp[p] = s;
    d_perm[p] = e;
}

// ---------------------------------------------------------------------------
// Gates for all 3 layers, written directly in CSR order.
// ---------------------------------------------------------------------------
__global__ void gatecsr_kernel(const float* __restrict__ ea,
                               const float* __restrict__ ew1,
                               const float* __restrict__ eb1,
                               const float* __restrict__ ew2,
                               const float* __restrict__ eb2) {
    __shared__ float W1[LL * 3 * 16];
    __shared__ float B1[LL * 16];
    __shared__ float W2[LL * 16];
    __shared__ float B2[LL];
    for (int i = threadIdx.x; i < LL * 3 * 16; i += blockDim.x) W1[i] = ew1[i];
    if (threadIdx.x < LL * 16) {
        B1[threadIdx.x] = eb1[threadIdx.x];
        W2[threadIdx.x] = ew2[threadIdx.x];
    }
    if (threadIdx.x < LL) B2[threadIdx.x] = eb2[threadIdx.x];
    __syncthreads();

    int p = blockIdx.x * blockDim.x + threadIdx.x;   // EE % 256 == 0
    int e = d_perm[p];
    float a0 = ea[e * 3 + 0];
    float a1 = ea[e * 3 + 1];
    float a2 = ea[e * 3 + 2];
#pragma unroll
    for (int l = 0; l < LL; l++) {
        float z = B2[l];
#pragma unroll
        for (int k = 0; k < 16; k++) {
            float hk = B1[l * 16 + k];
            hk = fmaf(a0, W1[l * 48 + 0 * 16 + k], hk);
            hk = fmaf(a1, W1[l * 48 + 1 * 16 + k], hk);
            hk = fmaf(a2, W1[l * 48 + 2 * 16 + k], hk);
            z = fmaf(fmaxf(hk, 0.f), W2[l * 16 + k], z);
        }
        d_gcsr[l * EE + p] = 1.f / (1.f + __expf(-z));
    }
}

// ---------------------------------------------------------------------------
// Fused layer: warp per 4 dst nodes.
//   Phase A (per node): quarter-warp gather — 4 edges concurrently, each
//   8-lane group covers the 64-float row with 2 float4 loads/lane; edge
//   loop unrolled x2 => 4 independent loads in flight per lane.
//   Phase B: joint 128->64 MLP for all 4 nodes (FFMA2, smem weights).
//   Phase C (per node): residual + LayerNorm, write hout.
// ---------------------------------------------------------------------------
__global__ void __launch_bounds__(256)
layer_kernel(const float4* __restrict__ hin4,
             float* __restrict__ hout,
             const float* __restrict__ gcsr_l,
             const float* __restrict__ nw,
             const float* __restrict__ nb,
             const float* __restrict__ g,
             const float* __restrict__ b) {
    __shared__ float4 Wq[32 * 64];         // 32 KB  (k-interleaved float4)
    __shared__ float nbs[HH], gs[HH], bs[HH];
    __shared__ float ins[8][4 * 2 * HH];   // per-warp, 4 nodes x [h(64),agg(64)]

    {
        float* Wqf = (float*)Wq;
        for (int i = threadIdx.x; i < 2 * HH * HH; i += blockDim.x) {
            int k = i >> 6;        // 0..127
            int j = i & 63;        // 0..63
            Wqf[((k >> 2) * 64 + j) * 4 + (k & 3)] = nw[i];
        }
    }
    if (threadIdx.x < HH) {
        nbs[threadIdx.x] = nb[threadIdx.x];
        gs[threadIdx.x]  = g[threadIdx.x];
        bs[threadIdx.x]  = b[threadIdx.x];
    }
    __syncthreads();

    int warp = threadIdx.x >> 5;
    int lane = threadIdx.x & 31;
    int qtr  = lane >> 3;      // 0..3 : edge slot within iteration
    int ql   = lane & 7;       // float4 slot (covers ql and ql+8)

    float* insw = &ins[warp][0];
    float4* ins4 = (float4*)insw;
    uint32_t insAddr = (uint32_t)__cvta_generic_to_shared(insw);
    uint32_t wBase   = (uint32_t)__cvta_generic_to_shared(Wq) + lane * 16;

    for (int nd0 = (blockIdx.x * 8 + warp) * 4; nd0 < NN; nd0 += gridDim.x * 32) {
        // ---- Phase A: gather 4 nodes ----
#pragma unroll
        for (int nloc = 0; nloc < 4; nloc++) {
            int nd = nd0 + nloc;
            int e0 = d_off[nd];
            int e1 = d_off[nd + 1];

            // acc[0..3] -> float4 slot ql ; acc[4..7] -> slot ql+8
            float a0 = 0.f, a1 = 0.f, a2 = 0.f, a3 = 0.f;
            float a4 = 0.f, a5 = 0.f, a6 = 0.f, a7 = 0.f;
            float cw = 0.f;

            for (int base = e0; base < e1; base += 32) {
                int n = e1 - base;
                if (n > 32) n = 32;
                int   s = 0;
                float w = 0.f;
                if (lane < n) {
                    s = d_srcp[base + lane];
                    w = gcsr_l[base + lane];
                }
                cw += w;
                for (int i = 0; i < n; i += 8) {
                    int idx0 = i + qtr;
                    int idx1 = i + 4 + qtr;
                    int   s0 = __shfl_sync(0xffffffffu, s, idx0);
                    float w0 = __shfl_sync(0xffffffffu, w, idx0);
                    int   s1 = __shfl_sync(0xffffffffu, s, idx1);
                    float w1 = __shfl_sync(0xffffffffu, w, idx1);
                    // unconditional loads: out-of-range slots have s=0,w=0
                    float4 u0 = hin4[s0 * 16 + ql];
                    float4 u1 = hin4[s0 * 16 + 8 + ql];
                    float4 v0 = hin4[s1 * 16 + ql];
                    float4 v1 = hin4[s1 * 16 + 8 + ql];
                    a0 = fmaf(u0.x, w0, a0); a1 = fmaf(u0.y, w0, a1);
                    a2 = fmaf(u0.z, w0, a2); a3 = fmaf(u0.w, w0, a3);
                    a4 = fmaf(u1.x, w0, a4); a5 = fmaf(u1.y, w0, a5);
                    a6 = fmaf(u1.z, w0, a6); a7 = fmaf(u1.w, w0, a7);
                    a0 = fmaf(v0.x, w1, a0); a1 = fmaf(v0.y, w1, a1);
                    a2 = fmaf(v0.z, w1, a2); a3 = fmaf(v0.w, w1, a3);
                    a4 = fmaf(v1.x, w1, a4); a5 = fmaf(v1.y, w1, a5);
                    a6 = fmaf(v1.z, w1, a6); a7 = fmaf(v1.w, w1, a7);
                }
            }
            // reduce across the 4 quarter-groups (xor 8, then 16)
#pragma unroll
            for (int o = 8; o <= 16; o <<= 1) {
                a0 += __shfl_xor_sync(0xffffffffu, a0, o);
                a1 += __shfl_xor_sync(0xffffffffu, a1, o);
                a2 += __shfl_xor_sync(0xffffffffu, a2, o);
                a3 += __shfl_xor_sync(0xffffffffu, a3, o);
                a4 += __shfl_xor_sync(0xffffffffu, a4, o);
                a5 += __shfl_xor_sync(0xffffffffu, a5, o);
                a6 += __shfl_xor_sync(0xffffffffu, a6, o);
                a7 += __shfl_xor_sync(0xffffffffu, a7, o);
            }
#pragma unroll
            for (int o = 16; o > 0; o >>= 1)
                cw += __shfl_xor_sync(0xffffffffu, cw, o);

            float inv = 1.f / fmaxf(cw, 1e-12f);
            if (lane < 16)
                ins4[nloc * 32 + lane] = hin4[(size_t)nd * 16 + lane];
            if (qtr == 0)
                ins4[nloc * 32 + 16 + ql] =
                    make_float4(a0 * inv, a1 * inv, a2 * inv, a3 * inv);
            else if (qtr == 1)
                ins4[nloc * 32 + 16 + 8 + ql] =
                    make_float4(a4 * inv, a5 * inv, a6 * inv, a7 * inv);
            __syncwarp();
        }

        // ---- Phase B: joint MLP (FFMA2) ----
        unsigned long long aA0 = 0, aA1 = 0, aA2 = 0, aA3 = 0;  // out feat = lane
        unsigned long long aB0 = 0, aB1 = 0, aB2 = 0, aB3 = 0;  // out feat = lane+32
        uint32_t wAddr = wBase;
#pragma unroll
        for (int t = 0; t < 32; t++) {
            unsigned long long wa0, wa1, wb0, wb1;
            ldsv2u64(wAddr, wa0, wa1);          // j = lane,    k = 4t..4t+3
            ldsv2u64(wAddr + 512, wb0, wb1);    // j = lane+32
            unsigned long long x0, x1;
            ldsv2u64(insAddr + 0 * 512 + t * 16, x0, x1);
            ffma2(aA0, x0, wa0); ffma2(aA0, x1, wa1);
            ffma2(aB0, x0, wb0); ffma2(aB0, x1, wb1);
            ldsv2u64(insAddr + 1 * 512 + t * 16, x0, x1);
            ffma2(aA1, x0, wa0); ffma2(aA1, x1, wa1);
            ffma2(aB1, x0, wb0); ffma2(aB1, x1, wb1);
            ldsv2u64(insAddr + 2 * 512 + t * 16, x0, x1);
            ffma2(aA2, x0, wa0); ffma2(aA2, x1, wa1);
            ffma2(aB2, x0, wb0); ffma2(aB2, x1, wb1);
            ldsv2u64(insAddr + 3 * 512 + t * 16, x0, x1);
            ffma2(aA3, x0, wa0); ffma2(aA3, x1, wa1);
            ffma2(aB3, x0, wb0); ffma2(aB3, x1, wb1);
            wAddr += 1024;
        }

        float o0n[4], o1n[4];
        o0n[0] = pairsum(aA0); o0n[1] = pairsum(aA1);
        o0n[2] = pairsum(aA2); o0n[3] = pairsum(aA3);
        o1n[0] = pairsum(aB0); o1n[1] = pairsum(aB1);
        o1n[2] = pairsum(aB2); o1n[3] = pairsum(aB3);

        float bias0 = nbs[lane];
        float bias1 = nbs[lane + 32];

        // ---- Phase C: residual + LN per node ----
#pragma unroll
        for (int nloc = 0; nloc < 4; nloc++) {
            int nd = nd0 + nloc;
            float hl = insw[nloc * 128 + lane];
            float hh = insw[nloc * 128 + 32 + lane];
            float v0 = hl + fmaxf(o0n[nloc] + bias0, 0.f);
            float v1 = hh + fmaxf(o1n[nloc] + bias1, 0.f);

            float s1 = v0 + v1;
#pragma unroll
            for (int o = 16; o > 0; o >>= 1)
                s1 += __shfl_xor_sync(0xffffffffu, s1, o);
            float mu = s1 * (1.f / HH);
            float t0 = v0 - mu, t1 = v1 - mu;
            float s2 = t0 * t0 + t1 * t1;
#pragma unroll
            for (int o = 16; o > 0; o >>= 1)
                s2 += __shfl_xor_sync(0xffffffffu, s2, o);
            float var = s2 * (1.f / HH);
            float r = rsqrtf(var + 1e-5f);

            hout[nd * HH + lane]      = t0 * r * gs[lane]      + bs[lane];
            hout[nd * HH + 32 + lane] = t1 * r * gs[lane + 32] + bs[lane + 32];
        }
        __syncwarp();
    }
}

// ---------------------------------------------------------------------------
// Head: out = relu(h @ hw1 + hb1) @ hw2 + hb2
// ---------------------------------------------------------------------------
__global__ void head_kernel(const float* __restrict__ hsrc,
                            const float* __restrict__ hw1,
                            const float* __restrict__ hb1,
                            const float* __restrict__ hw2,
                            const float* __restrict__ hb2,
                            float* __restrict__ out) {
    __shared__ float W1[HH * 32];
    __shared__ float b1s[32], w2s[32];
    for (int i = threadIdx.x; i < HH * 32; i += blockDim.x) W1[i] = hw1[i];
    if (threadIdx.x < 32) {
        b1s[threadIdx.x] = hb1[threadIdx.x];
        w2s[threadIdx.x] = hw2[threadIdx.x];
    }
    __syncthreads();

    int lane = threadIdx.x & 31;
    int warp = threadIdx.x >> 5;
    float bb2 = hb2[0];

    for (int node = blockIdx.x * 8 + warp; node < NN; node += gridDim.x * 8) {
        float hlo = hsrc[node * HH + lane];
        float hhi = hsrc[node * HH + 32 + lane];
        float acc = b1s[lane];
#pragma unroll
        for (int k = 0; k < 32; k++) {
            float hk = __shfl_sync(0xffffffffu, hlo, k);
            acc = fmaf(hk, W1[k * 32 + lane], acc);
        }
#pragma unroll
        for (int k = 0; k < 32; k++) {
            float hk = __shfl_sync(0xffffffffu, hhi, k);
            acc = fmaf(hk, W1[(32 + k) * 32 + lane], acc);
        }
        float p = fmaxf(acc, 0.f) * w2s[lane];
#pragma unroll
        for (int o = 16; o > 0; o >>= 1)
            p += __shfl_xor_sync(0xffffffffu, p, o);
        if (lane == 0) out[node] = p + bb2;
    }
}

// ---------------------------------------------------------------------------
extern "C" void kernel_launch(void* const* d_in, const int* in_sizes, int n_in,
                              void* d_out, int out_size) {
    const float* x   = (const float*)d_in[0];
    const int*   ei  = (const int*)  d_in[1];
    const float* ea  = (const float*)d_in[2];
    const float* Wp  = (const float*)d_in[3];
    const float* bp  = (const float*)d_in[4];
    const float* ew1 = (const float*)d_in[5];
    const float* eb1 = (const float*)d_in[6];
    const float* ew2 = (const float*)d_in[7];
    const float* eb2 = (const float*)d_in[8];
    const float* nw  = (const float*)d_in[9];
    const float* nb  = (const float*)d_in[10];
    const float* lng = (const float*)d_in[11];
    const float* lnb = (const float*)d_in[12];
    const float* hw1 = (const float*)d_in[13];
    const float* hb1 = (const float*)d_in[14];
    const float* hw2 = (const float*)d_in[15];
    const float* hb2 = (const float*)d_in[16];
    float* out = (float*)d_out;

    void* degPtr = nullptr;
    cudaGetSymbolAddress(&degPtr, d_deg);
    float* hA = nullptr; float* hB = nullptr; float* gcsr = nullptr;
    cudaGetSymbolAddress((void**)&hA, d_hA);
    cudaGetSymbolAddress((void**)&hB, d_hB);
    cudaGetSymbolAddress((void**)&gcsr, d_gcsr);

    proj_kernel<<<(NN * HH + 255) / 256, 256>>>(x, Wp, bp);

    cudaMemsetAsync(degPtr, 0, (size_t)NN * sizeof(int));
    count_kernel<<<(EE + 255) / 256, 256>>>(ei);
    partial_kernel<<<49, 1024>>>();
    base_kernel<<<1, 64>>>();
    offs_kernel<<<49, 1024>>>();
    fill_kernel<<<(EE + 255) / 256, 256>>>(ei);
    gatecsr_kernel<<<EE / 256, 256>>>(ea, ew1, eb1, ew2, eb2);

    for (int l = 0; l < LL; l++) {
        const float* hin  = (l & 1) ? hB : hA;
        float*       hout = (l & 1) ? hA : hB;
        layer_kernel<<<592, 256>>>((const float4*)hin, hout,
                                   gcsr + (size_t)l * EE,
                                   nw + l * 2 * HH * HH, nb + l * HH,
                                   lng + l * HH, lnb + l * HH);
    }

    head_kernel<<<592, 256>>>(hB, hw1, hb1, hw2, hb2, out);
}